// round 9
// baseline (speedup 1.0000x reference)
#include <cuda_runtime.h>
#include <cstdint>
#include <math.h>

#define NN 100000
#define NE 1600000
#define EPS 1e-5f

// ================= device scratch =================
__device__ int   g_cnt[NN];
__device__ int   g_off[NN + 1];
__device__ int   g_cur[NN];
__device__ float g_inv[NN];
__device__ int   g_col[NE];
__device__ float g_agg[(size_t)NN * 128];
__device__ float g_preA[(size_t)NN * 128];
__device__ float g_preB[(size_t)NN * 128];
__device__ float g_sum[128];
__device__ float g_ssq[128];
__device__ float g_scale[128];
__device__ float g_shift[128];

__device__ __forceinline__ uint32_t tf32u(float x) {
    uint32_t y; asm("cvt.rna.tf32.f32 %0, %1;" : "=r"(y) : "f"(x)); return y;
}

// ================= CSR build =================
__global__ void zero_cnt_kernel() {
    int i = blockIdx.x * blockDim.x + threadIdx.x;
    if (i < NN) g_cnt[i] = 0;
}
__global__ void hist_kernel(const int* __restrict__ dst) {
    int e = blockIdx.x * blockDim.x + threadIdx.x;
    if (e < NE) atomicAdd(&g_cnt[dst[e]], 1);
}
__global__ void scan_kernel() {
    __shared__ int s[1024];
    const int t = threadIdx.x;
    const int chunk = (NN + 1023) / 1024;
    int start = t * chunk;
    int end = start + chunk; if (end > NN) end = NN;
    if (start > NN) start = NN;
    int sum = 0;
    for (int i = start; i < end; i++) sum += g_cnt[i];
    s[t] = sum;
    __syncthreads();
    for (int off = 1; off < 1024; off <<= 1) {
        int v = (t >= off) ? s[t - off] : 0;
        __syncthreads();
        s[t] += v;
        __syncthreads();
    }
    int excl = (t == 0) ? 0 : s[t - 1];
    for (int i = start; i < end; i++) {
        int c = g_cnt[i];
        g_off[i] = excl;
        g_cur[i] = excl;
        g_inv[i] = 1.0f / fmaxf((float)c, 1.0f);
        excl += c;
    }
    if (t == 1023) g_off[NN] = s[1023];
}
__global__ void fill_kernel(const int* __restrict__ src, const int* __restrict__ dst) {
    int e = blockIdx.x * blockDim.x + threadIdx.x;
    if (e < NE) {
        int d = dst[e];
        int p = atomicAdd(&g_cur[d], 1);
        g_col[p] = src[e];
    }
}

// ====== mean aggregation (warp/node), 4-way MLP, fused BN+ReLU/zero ======
template <bool FUSE>
__global__ void agg_kernel(const float* __restrict__ hin) {
    if (blockIdx.x == 0 && threadIdx.x < 128) {   // zero next layer's BN stats
        g_sum[threadIdx.x] = 0.f;
        g_ssq[threadIdx.x] = 0.f;
    }
    int w = (blockIdx.x * blockDim.x + threadIdx.x) >> 5;
    if (w >= NN) return;
    int lane = threadIdx.x & 31;
    const float4* h4 = (const float4*)hin;
    float4 sc, sh;
    if (FUSE) {
        sc = *(const float4*)(g_scale + lane * 4);
        sh = *(const float4*)(g_shift + lane * 4);
    }
    float4 a0 = make_float4(0.f, 0.f, 0.f, 0.f);
    float4 a1 = a0, a2 = a0, a3 = a0;
    const int e0 = g_off[w], e1 = g_off[w + 1];
    int j = e0;
    for (; j + 3 < e1; j += 4) {
        int s0 = g_col[j], s1 = g_col[j + 1], s2 = g_col[j + 2], s3 = g_col[j + 3];
        float4 v0 = __ldg(&h4[(size_t)s0 * 32 + lane]);
        float4 v1 = __ldg(&h4[(size_t)s1 * 32 + lane]);
        float4 v2 = __ldg(&h4[(size_t)s2 * 32 + lane]);
        float4 v3 = __ldg(&h4[(size_t)s3 * 32 + lane]);
        if (FUSE) {
            v0.x = fmaxf(fmaf(v0.x, sc.x, sh.x), 0.f); v0.y = fmaxf(fmaf(v0.y, sc.y, sh.y), 0.f);
            v0.z = fmaxf(fmaf(v0.z, sc.z, sh.z), 0.f); v0.w = fmaxf(fmaf(v0.w, sc.w, sh.w), 0.f);
            v1.x = fmaxf(fmaf(v1.x, sc.x, sh.x), 0.f); v1.y = fmaxf(fmaf(v1.y, sc.y, sh.y), 0.f);
            v1.z = fmaxf(fmaf(v1.z, sc.z, sh.z), 0.f); v1.w = fmaxf(fmaf(v1.w, sc.w, sh.w), 0.f);
            v2.x = fmaxf(fmaf(v2.x, sc.x, sh.x), 0.f); v2.y = fmaxf(fmaf(v2.y, sc.y, sh.y), 0.f);
            v2.z = fmaxf(fmaf(v2.z, sc.z, sh.z), 0.f); v2.w = fmaxf(fmaf(v2.w, sc.w, sh.w), 0.f);
            v3.x = fmaxf(fmaf(v3.x, sc.x, sh.x), 0.f); v3.y = fmaxf(fmaf(v3.y, sc.y, sh.y), 0.f);
            v3.z = fmaxf(fmaf(v3.z, sc.z, sh.z), 0.f); v3.w = fmaxf(fmaf(v3.w, sc.w, sh.w), 0.f);
        }
        a0.x += v0.x; a0.y += v0.y; a0.z += v0.z; a0.w += v0.w;
        a1.x += v1.x; a1.y += v1.y; a1.z += v1.z; a1.w += v1.w;
        a2.x += v2.x; a2.y += v2.y; a2.z += v2.z; a2.w += v2.w;
        a3.x += v3.x; a3.y += v3.y; a3.z += v3.z; a3.w += v3.w;
    }
    for (; j < e1; j++) {
        int s = g_col[j];
        float4 v = __ldg(&h4[(size_t)s * 32 + lane]);
        if (FUSE) {
            v.x = fmaxf(fmaf(v.x, sc.x, sh.x), 0.f);
            v.y = fmaxf(fmaf(v.y, sc.y, sh.y), 0.f);
            v.z = fmaxf(fmaf(v.z, sc.z, sh.z), 0.f);
            v.w = fmaxf(fmaf(v.w, sc.w, sh.w), 0.f);
        }
        a0.x += v.x; a0.y += v.y; a0.z += v.z; a0.w += v.w;
    }
    float4 acc = make_float4((a0.x + a1.x) + (a2.x + a3.x),
                             (a0.y + a1.y) + (a2.y + a3.y),
                             (a0.z + a1.z) + (a2.z + a3.z),
                             (a0.w + a1.w) + (a2.w + a3.w));
    float iv = g_inv[w];
    ((float4*)g_agg)[(size_t)w * 32 + lane] =
        make_float4(acc.x * iv, acc.y * iv, acc.z * iv, acc.w * iv);
}

// ================= tf32 mma.sync dual-GEMM, K-streamed B ==================
// (measured-best structure from the 720us kernel)
template <int COUT, bool FUSE>
__global__ __launch_bounds__(256) void gemm_mma_kernel(
    const float* __restrict__ Aagg, const float* __restrict__ Ah,
    const float* __restrict__ Wl, const float* __restrict__ Wr,
    const float* __restrict__ bias, float* __restrict__ outp)
{
    constexpr int STR = 36;
    constexpr int NT = COUT / 16;
    constexpr int BITER = COUT / 32;
    extern __shared__ float smem[];
    float* As = smem;                          // [2][128][36]
    float* Bs = smem + 2 * 128 * STR;          // [2][COUT][36]

    const int tid = threadIdx.x, wid = tid >> 5, lane = tid & 31;
    const int g = lane >> 2, tig = lane & 3;
    const int row0 = blockIdx.x * 128;
    const int m0 = (wid >> 1) * 32;
    const int n0 = (wid & 1) * (COUT / 2);

    // ---- stage chunk 0: A (agg) + B (Wl) ----
#pragma unroll
    for (int t = 0; t < 4; t++) {
        int i = tid + t * 256;
        int row = i >> 3, k4 = i & 7;
        int grow = row0 + row;
        float4 v = make_float4(0.f, 0.f, 0.f, 0.f);
        if (grow < NN) v = *(const float4*)(Aagg + (size_t)grow * 128 + k4 * 4);
        uint4 u = make_uint4(tf32u(v.x), tf32u(v.y), tf32u(v.z), tf32u(v.w));
        *(uint4*)(As + row * STR + k4 * 4) = u;
    }
#pragma unroll
    for (int t = 0; t < BITER; t++) {
        int i = tid + t * 256;
        int n = i >> 3, k4 = i & 7;
        float4 v = *(const float4*)(Wl + n * 128 + k4 * 4);
        uint4 u = make_uint4(tf32u(v.x), tf32u(v.y), tf32u(v.z), tf32u(v.w));
        *(uint4*)(Bs + n * STR + k4 * 4) = u;
    }
    __syncthreads();

    float acc[2][NT][4];
#pragma unroll
    for (int mt = 0; mt < 2; mt++)
#pragma unroll
        for (int nt = 0; nt < NT; nt++)
#pragma unroll
            for (int j = 0; j < 4; j++) acc[mt][nt][j] = 0.f;

    for (int c = 0; c < 8; c++) {
        float4 rA[4], rB[BITER];
        if (c < 7) {
            int cn = c + 1;
            const float* src = (cn < 4) ? Aagg : Ah;
            const float* W = (cn < 4) ? Wl : Wr;
            const bool dofuse = FUSE && (cn >= 4);
            int koff = (cn & 3) * 32;
#pragma unroll
            for (int t = 0; t < 4; t++) {
                int i = tid + t * 256;
                int row = i >> 3, k4 = i & 7;
                int grow = row0 + row;
                rA[t] = make_float4(0.f, 0.f, 0.f, 0.f);
                if (grow < NN) {
                    float4 v = *(const float4*)(src + (size_t)grow * 128 + koff + k4 * 4);
                    if (dofuse) {
                        float4 sc = *(const float4*)(g_scale + koff + k4 * 4);
                        float4 sh = *(const float4*)(g_shift + koff + k4 * 4);
                        v.x = fmaxf(fmaf(v.x, sc.x, sh.x), 0.f);
                        v.y = fmaxf(fmaf(v.y, sc.y, sh.y), 0.f);
                        v.z = fmaxf(fmaf(v.z, sc.z, sh.z), 0.f);
                        v.w = fmaxf(fmaf(v.w, sc.w, sh.w), 0.f);
                    }
                    rA[t] = v;
                }
            }
#pragma unroll
            for (int t = 0; t < BITER; t++) {
                int i = tid + t * 256;
                int n = i >> 3, k4 = i & 7;
                rB[t] = *(const float4*)(W + n * 128 + koff + k4 * 4);
            }
        }
        const float* Ab = As + (c & 1) * 128 * STR;
        const float* Bb = Bs + (c & 1) * COUT * STR;
#pragma unroll
        for (int kk = 0; kk < 32; kk += 8) {
            uint32_t a[2][4], b[NT][2];
#pragma unroll
            for (int mt = 0; mt < 2; mt++) {
                const float* ap = Ab + (m0 + mt * 16 + g) * STR + kk + tig;
                a[mt][0] = __float_as_uint(ap[0]);
                a[mt][1] = __float_as_uint(ap[8 * STR]);
                a[mt][2] = __float_as_uint(ap[4]);
                a[mt][3] = __float_as_uint(ap[8 * STR + 4]);
            }
#pragma unroll
            for (int nt = 0; nt < NT; nt++) {
                const float* bp = Bb + (n0 + nt * 8 + g) * STR + kk + tig;
                b[nt][0] = __float_as_uint(bp[0]);
                b[nt][1] = __float_as_uint(bp[4]);
            }
#pragma unroll
            for (int mt = 0; mt < 2; mt++)
#pragma unroll
                for (int nt = 0; nt < NT; nt++)
                    asm volatile(
                        "mma.sync.aligned.m16n8k8.row.col.f32.tf32.tf32.f32 "
                        "{%0,%1,%2,%3}, {%4,%5,%6,%7}, {%8,%9}, {%0,%1,%2,%3};"
                        : "+f"(acc[mt][nt][0]), "+f"(acc[mt][nt][1]),
                          "+f"(acc[mt][nt][2]), "+f"(acc[mt][nt][3])
                        : "r"(a[mt][0]), "r"(a[mt][1]), "r"(a[mt][2]), "r"(a[mt][3]),
                          "r"(b[nt][0]), "r"(b[nt][1]));
        }
        __syncthreads();
        if (c < 7) {
            float* dA = As + ((c + 1) & 1) * 128 * STR;
            float* dB = Bs + ((c + 1) & 1) * COUT * STR;
#pragma unroll
            for (int t = 0; t < 4; t++) {
                int i = tid + t * 256;
                int row = i >> 3, k4 = i & 7;
                uint4 u = make_uint4(tf32u(rA[t].x), tf32u(rA[t].y),
                                     tf32u(rA[t].z), tf32u(rA[t].w));
                *(uint4*)(dA + row * STR + k4 * 4) = u;
            }
#pragma unroll
            for (int t = 0; t < BITER; t++) {
                int i = tid + t * 256;
                int n = i >> 3, k4 = i & 7;
                uint4 u = make_uint4(tf32u(rB[t].x), tf32u(rB[t].y),
                                     tf32u(rB[t].z), tf32u(rB[t].w));
                *(uint4*)(dB + n * STR + k4 * 4) = u;
            }
            __syncthreads();
        }
    }

    // ---- epilogue: bias + store + fused BN stats ----
    float ssum[NT][2], sq[NT][2];
#pragma unroll
    for (int nt = 0; nt < NT; nt++) {
        ssum[nt][0] = ssum[nt][1] = 0.f;
        sq[nt][0] = sq[nt][1] = 0.f;
    }
#pragma unroll
    for (int mt = 0; mt < 2; mt++) {
        int rA2 = row0 + m0 + mt * 16 + g;
        int rB2 = rA2 + 8;
#pragma unroll
        for (int nt = 0; nt < NT; nt++) {
            int col = n0 + nt * 8 + tig * 2;
            float b0 = bias[col], b1 = bias[col + 1];
            float o00 = acc[mt][nt][0] + b0, o01 = acc[mt][nt][1] + b1;
            float o10 = acc[mt][nt][2] + b0, o11 = acc[mt][nt][3] + b1;
            if (rA2 < NN) {
                *(float2*)(outp + (size_t)rA2 * COUT + col) = make_float2(o00, o01);
                ssum[nt][0] += o00; sq[nt][0] += o00 * o00;
                ssum[nt][1] += o01; sq[nt][1] += o01 * o01;
            }
            if (rB2 < NN) {
                *(float2*)(outp + (size_t)rB2 * COUT + col) = make_float2(o10, o11);
                ssum[nt][0] += o10; sq[nt][0] += o10 * o10;
                ssum[nt][1] += o11; sq[nt][1] += o11 * o11;
            }
        }
    }
#pragma unroll
    for (int nt = 0; nt < NT; nt++)
#pragma unroll
        for (int j = 0; j < 2; j++) {
            float s = ssum[nt][j], q = sq[nt][j];
#pragma unroll
            for (int off = 4; off < 32; off <<= 1) {
                s += __shfl_xor_sync(0xFFFFFFFFu, s, off);
                q += __shfl_xor_sync(0xFFFFFFFFu, q, off);
            }
            if (g == 0) {
                int col = n0 + nt * 8 + tig * 2 + j;
                atomicAdd(&g_sum[col], s);
                atomicAdd(&g_ssq[col], q);
            }
        }
}

// ================= BN finalize + final norm pass =================
__global__ void bnfinal_kernel(const float* __restrict__ gamma,
                               const float* __restrict__ beta, int C) {
    int c = threadIdx.x;
    if (c < C) {
        float m = g_sum[c] * (1.0f / (float)NN);
        float v = g_ssq[c] * (1.0f / (float)NN) - m * m;
        float s = gamma[c] * rsqrtf(v + EPS);
        g_scale[c] = s;
        g_shift[c] = beta[c] - m * s;
    }
}
template <bool RELU, int C>
__global__ void norm_kernel(const float* __restrict__ inp, float* __restrict__ outp) {
    const int total4 = NN * C / 4;
    const float4* p4 = (const float4*)inp;
    float4* o4 = (float4*)outp;
    for (int i = blockIdx.x * blockDim.x + threadIdx.x; i < total4;
         i += gridDim.x * blockDim.x) {
        int c = (i * 4) & (C - 1);
        float4 v = p4[i];
        float4 sc = *(const float4*)(g_scale + c);
        float4 sh = *(const float4*)(g_shift + c);
        float4 r;
        r.x = fmaf(v.x, sc.x, sh.x); r.y = fmaf(v.y, sc.y, sh.y);
        r.z = fmaf(v.z, sc.z, sh.z); r.w = fmaf(v.w, sc.w, sh.w);
        if (RELU) {
            r.x = fmaxf(r.x, 0.f); r.y = fmaxf(r.y, 0.f);
            r.z = fmaxf(r.z, 0.f); r.w = fmaxf(r.w, 0.f);
        }
        o4[i] = r;
    }
}

// ================= launch =================
extern "C" void kernel_launch(void* const* d_in, const int* in_sizes, int n_in,
                              void* d_out, int out_size) {
    const float* x    = (const float*)d_in[0];
    const int*   ei   = (const int*)d_in[1];
    const int*   esrc = ei;
    const int*   edst = ei + NE;
    const float* Wl0 = (const float*)d_in[2];
    const float* bl0 = (const float*)d_in[3];
    const float* Wr0 = (const float*)d_in[4];
    const float* ga0 = (const float*)d_in[5];
    const float* be0 = (const float*)d_in[6];
    const float* Wl1 = (const float*)d_in[7];
    const float* bl1 = (const float*)d_in[8];
    const float* Wr1 = (const float*)d_in[9];
    const float* ga1 = (const float*)d_in[10];
    const float* be1 = (const float*)d_in[11];
    const float* Wl2 = (const float*)d_in[12];
    const float* bl2 = (const float*)d_in[13];
    const float* Wr2 = (const float*)d_in[14];
    const float* ga2 = (const float*)d_in[15];
    const float* be2 = (const float*)d_in[16];
    float* out = (float*)d_out;

    const int smem128 = (2 * 128 * 36 + 2 * 128 * 36) * sizeof(float);  // 73728
    const int smem64  = (2 * 128 * 36 + 2 * 64 * 36) * sizeof(float);   // 55296
    cudaFuncSetAttribute(gemm_mma_kernel<128, false>, cudaFuncAttributeMaxDynamicSharedMemorySize, smem128);
    cudaFuncSetAttribute(gemm_mma_kernel<128, true>,  cudaFuncAttributeMaxDynamicSharedMemorySize, smem128);
    cudaFuncSetAttribute(gemm_mma_kernel<64, true>,   cudaFuncAttributeMaxDynamicSharedMemorySize, smem64);

    float *preA = nullptr, *preB = nullptr, *aggp = nullptr;
    cudaGetSymbolAddress((void**)&preA, g_preA);
    cudaGetSymbolAddress((void**)&preB, g_preB);
    cudaGetSymbolAddress((void**)&aggp, g_agg);

    // ---- CSR build ----
    zero_cnt_kernel<<<(NN + 255) / 256, 256>>>();
    hist_kernel<<<NE / 256, 256>>>(edst);
    scan_kernel<<<1, 1024>>>();
    fill_kernel<<<NE / 256, 256>>>(esrc, edst);

    const int aggBlocks = NN / 8;
    const int gemmBlocks = (NN + 127) / 128;

    // ---- layer 0: x -> preA ----
    agg_kernel<false><<<aggBlocks, 256>>>(x);
    gemm_mma_kernel<128, false><<<gemmBlocks, 256, smem128>>>(aggp, x, Wl0, Wr0, bl0, preA);
    bnfinal_kernel<<<1, 128>>>(ga0, be0, 128);

    // ---- layer 1: relu(bn(preA)) -> preB ----
    agg_kernel<true><<<aggBlocks, 256>>>(preA);
    gemm_mma_kernel<128, true><<<gemmBlocks, 256, smem128>>>(aggp, preA, Wl1, Wr1, bl1, preB);
    bnfinal_kernel<<<1, 128>>>(ga1, be1, 128);

    // ---- layer 2: relu(bn(preB)) -> preA (64 cols) ----
    agg_kernel<true><<<aggBlocks, 256>>>(preB);
    gemm_mma_kernel<64, true><<<gemmBlocks, 256, smem64>>>(aggp, preB, Wl2, Wr2, bl2, preA);
    bnfinal_kernel<<<1, 64>>>(ga2, be2, 64);

    // ---- final normalize (no relu) ----
    norm_kernel<false, 64><<<2048, 256>>>(preA, out);
}

// round 10
// speedup vs baseline: 1.0767x; 1.0767x over previous
#include <cuda_runtime.h>
#include <cuda_fp16.h>
#include <cstdint>
#include <math.h>

#define NN 100000
#define NE 1600000
#define EPS 1e-5f

// ================= device scratch =================
__device__ int    g_cnt[NN];
__device__ int    g_off[NN + 1];
__device__ int    g_cur[NN];
__device__ float  g_inv[NN];
__device__ int    g_col[NE];
__device__ float  g_agg[(size_t)NN * 128];
__device__ float  g_preA[(size_t)NN * 128];
__device__ float  g_preB[(size_t)NN * 128];
__device__ __half g_h16[(size_t)NN * 128];     // fp16 mirror of gather source
__device__ float  g_sum[128];
__device__ float  g_ssq[128];
__device__ float  g_scale[128];
__device__ float  g_shift[128];

__device__ __forceinline__ uint32_t tf32u(float x) {
    uint32_t y; asm("cvt.rna.tf32.f32 %0, %1;" : "=r"(y) : "f"(x)); return y;
}

// ================= CSR build =================
__global__ void zero_cnt_kernel() {
    int i = blockIdx.x * blockDim.x + threadIdx.x;
    if (i < NN) g_cnt[i] = 0;
}
__global__ void hist_kernel(const int* __restrict__ dst) {
    int e = blockIdx.x * blockDim.x + threadIdx.x;
    if (e < NE) atomicAdd(&g_cnt[dst[e]], 1);
}
__global__ void scan_kernel() {
    __shared__ int s[1024];
    const int t = threadIdx.x;
    const int chunk = (NN + 1023) / 1024;
    int start = t * chunk;
    int end = start + chunk; if (end > NN) end = NN;
    if (start > NN) start = NN;
    int sum = 0;
    for (int i = start; i < end; i++) sum += g_cnt[i];
    s[t] = sum;
    __syncthreads();
    for (int off = 1; off < 1024; off <<= 1) {
        int v = (t >= off) ? s[t - off] : 0;
        __syncthreads();
        s[t] += v;
        __syncthreads();
    }
    int excl = (t == 0) ? 0 : s[t - 1];
    for (int i = start; i < end; i++) {
        int c = g_cnt[i];
        g_off[i] = excl;
        g_cur[i] = excl;
        g_inv[i] = 1.0f / fmaxf((float)c, 1.0f);
        excl += c;
    }
    if (t == 1023) g_off[NN] = s[1023];
}
__global__ void fill_kernel(const int* __restrict__ src, const int* __restrict__ dst) {
    int e = blockIdx.x * blockDim.x + threadIdx.x;
    if (e < NE) {
        int d = dst[e];
        int p = atomicAdd(&g_cur[d], 1);
        g_col[p] = src[e];
    }
}

// ============ x -> fp16 mirror (layer-0 gather source) ============
__global__ void x2h_kernel(const float* __restrict__ x) {
    int i = blockIdx.x * blockDim.x + threadIdx.x;
    if (i < NN * 32) {
        float4 v = ((const float4*)x)[i];
        __half2 a = __floats2half2_rn(v.x, v.y);
        __half2 b = __floats2half2_rn(v.z, v.w);
        uint2 o;
        o.x = *(uint32_t*)&a;
        o.y = *(uint32_t*)&b;
        ((uint2*)g_h16)[i] = o;
    }
}

// ====== mean aggregation (warp/node) over fp16 mirror, fused BN+ReLU ======
template <bool FUSE>
__global__ void agg_kernel() {
    if (blockIdx.x == 0 && threadIdx.x < 128) {   // zero next layer's BN stats
        g_sum[threadIdx.x] = 0.f;
        g_ssq[threadIdx.x] = 0.f;
    }
    int w = (blockIdx.x * blockDim.x + threadIdx.x) >> 5;
    if (w >= NN) return;
    int lane = threadIdx.x & 31;
    const uint2* h2 = (const uint2*)g_h16;       // 4 halves per lane
    float4 sc, sh;
    if (FUSE) {
        sc = *(const float4*)(g_scale + lane * 4);
        sh = *(const float4*)(g_shift + lane * 4);
    }
    float4 acc = make_float4(0.f, 0.f, 0.f, 0.f);
    int e0 = g_off[w], e1 = g_off[w + 1];
    for (int j = e0; j < e1; j++) {
        int s = g_col[j];
        uint2 u = __ldg(&h2[(size_t)s * 32 + lane]);
        __half2 h0 = *(__half2*)&u.x;
        __half2 h1 = *(__half2*)&u.y;
        float2 f0 = __half22float2(h0);
        float2 f1 = __half22float2(h1);
        float4 v = make_float4(f0.x, f0.y, f1.x, f1.y);
        if (FUSE) {
            v.x = fmaxf(fmaf(v.x, sc.x, sh.x), 0.f);
            v.y = fmaxf(fmaf(v.y, sc.y, sh.y), 0.f);
            v.z = fmaxf(fmaf(v.z, sc.z, sh.z), 0.f);
            v.w = fmaxf(fmaf(v.w, sc.w, sh.w), 0.f);
        }
        acc.x += v.x; acc.y += v.y; acc.z += v.z; acc.w += v.w;
    }
    float iv = g_inv[w];
    ((float4*)g_agg)[(size_t)w * 32 + lane] =
        make_float4(acc.x * iv, acc.y * iv, acc.z * iv, acc.w * iv);
}

// ================= tf32 mma.sync dual-GEMM, K-streamed B ==================
// (measured-best 720us structure; COUT==128 additionally writes fp16 mirror)
template <int COUT, bool FUSE>
__global__ __launch_bounds__(256) void gemm_mma_kernel(
    const float* __restrict__ Aagg, const float* __restrict__ Ah,
    const float* __restrict__ Wl, const float* __restrict__ Wr,
    const float* __restrict__ bias, float* __restrict__ outp)
{
    constexpr int STR = 36;
    constexpr int NT = COUT / 16;
    constexpr int BITER = COUT / 32;
    extern __shared__ float smem[];
    float* As = smem;                          // [2][128][36]
    float* Bs = smem + 2 * 128 * STR;          // [2][COUT][36]

    const int tid = threadIdx.x, wid = tid >> 5, lane = tid & 31;
    const int g = lane >> 2, tig = lane & 3;
    const int row0 = blockIdx.x * 128;
    const int m0 = (wid >> 1) * 32;
    const int n0 = (wid & 1) * (COUT / 2);

    // ---- stage chunk 0: A (agg) + B (Wl) ----
#pragma unroll
    for (int t = 0; t < 4; t++) {
        int i = tid + t * 256;
        int row = i >> 3, k4 = i & 7;
        int grow = row0 + row;
        float4 v = make_float4(0.f, 0.f, 0.f, 0.f);
        if (grow < NN) v = *(const float4*)(Aagg + (size_t)grow * 128 + k4 * 4);
        uint4 u = make_uint4(tf32u(v.x), tf32u(v.y), tf32u(v.z), tf32u(v.w));
        *(uint4*)(As + row * STR + k4 * 4) = u;
    }
#pragma unroll
    for (int t = 0; t < BITER; t++) {
        int i = tid + t * 256;
        int n = i >> 3, k4 = i & 7;
        float4 v = *(const float4*)(Wl + n * 128 + k4 * 4);
        uint4 u = make_uint4(tf32u(v.x), tf32u(v.y), tf32u(v.z), tf32u(v.w));
        *(uint4*)(Bs + n * STR + k4 * 4) = u;
    }
    __syncthreads();

    float acc[2][NT][4];
#pragma unroll
    for (int mt = 0; mt < 2; mt++)
#pragma unroll
        for (int nt = 0; nt < NT; nt++)
#pragma unroll
            for (int j = 0; j < 4; j++) acc[mt][nt][j] = 0.f;

    for (int c = 0; c < 8; c++) {
        float4 rA[4], rB[BITER];
        if (c < 7) {
            int cn = c + 1;
            const float* src = (cn < 4) ? Aagg : Ah;
            const float* W = (cn < 4) ? Wl : Wr;
            const bool dofuse = FUSE && (cn >= 4);
            int koff = (cn & 3) * 32;
#pragma unroll
            for (int t = 0; t < 4; t++) {
                int i = tid + t * 256;
                int row = i >> 3, k4 = i & 7;
                int grow = row0 + row;
                rA[t] = make_float4(0.f, 0.f, 0.f, 0.f);
                if (grow < NN) {
                    float4 v = *(const float4*)(src + (size_t)grow * 128 + koff + k4 * 4);
                    if (dofuse) {
                        float4 sc = *(const float4*)(g_scale + koff + k4 * 4);
                        float4 sh = *(const float4*)(g_shift + koff + k4 * 4);
                        v.x = fmaxf(fmaf(v.x, sc.x, sh.x), 0.f);
                        v.y = fmaxf(fmaf(v.y, sc.y, sh.y), 0.f);
                        v.z = fmaxf(fmaf(v.z, sc.z, sh.z), 0.f);
                        v.w = fmaxf(fmaf(v.w, sc.w, sh.w), 0.f);
                    }
                    rA[t] = v;
                }
            }
#pragma unroll
            for (int t = 0; t < BITER; t++) {
                int i = tid + t * 256;
                int n = i >> 3, k4 = i & 7;
                rB[t] = *(const float4*)(W + n * 128 + koff + k4 * 4);
            }
        }
        const float* Ab = As + (c & 1) * 128 * STR;
        const float* Bb = Bs + (c & 1) * COUT * STR;
#pragma unroll
        for (int kk = 0; kk < 32; kk += 8) {
            uint32_t a[2][4], b[NT][2];
#pragma unroll
            for (int mt = 0; mt < 2; mt++) {
                const float* ap = Ab + (m0 + mt * 16 + g) * STR + kk + tig;
                a[mt][0] = __float_as_uint(ap[0]);
                a[mt][1] = __float_as_uint(ap[8 * STR]);
                a[mt][2] = __float_as_uint(ap[4]);
                a[mt][3] = __float_as_uint(ap[8 * STR + 4]);
            }
#pragma unroll
            for (int nt = 0; nt < NT; nt++) {
                const float* bp = Bb + (n0 + nt * 8 + g) * STR + kk + tig;
                b[nt][0] = __float_as_uint(bp[0]);
                b[nt][1] = __float_as_uint(bp[4]);
            }
#pragma unroll
            for (int mt = 0; mt < 2; mt++)
#pragma unroll
                for (int nt = 0; nt < NT; nt++)
                    asm volatile(
                        "mma.sync.aligned.m16n8k8.row.col.f32.tf32.tf32.f32 "
                        "{%0,%1,%2,%3}, {%4,%5,%6,%7}, {%8,%9}, {%0,%1,%2,%3};"
                        : "+f"(acc[mt][nt][0]), "+f"(acc[mt][nt][1]),
                          "+f"(acc[mt][nt][2]), "+f"(acc[mt][nt][3])
                        : "r"(a[mt][0]), "r"(a[mt][1]), "r"(a[mt][2]), "r"(a[mt][3]),
                          "r"(b[nt][0]), "r"(b[nt][1]));
        }
        __syncthreads();
        if (c < 7) {
            float* dA = As + ((c + 1) & 1) * 128 * STR;
            float* dB = Bs + ((c + 1) & 1) * COUT * STR;
#pragma unroll
            for (int t = 0; t < 4; t++) {
                int i = tid + t * 256;
                int row = i >> 3, k4 = i & 7;
                uint4 u = make_uint4(tf32u(rA[t].x), tf32u(rA[t].y),
                                     tf32u(rA[t].z), tf32u(rA[t].w));
                *(uint4*)(dA + row * STR + k4 * 4) = u;
            }
#pragma unroll
            for (int t = 0; t < BITER; t++) {
                int i = tid + t * 256;
                int n = i >> 3, k4 = i & 7;
                uint4 u = make_uint4(tf32u(rB[t].x), tf32u(rB[t].y),
                                     tf32u(rB[t].z), tf32u(rB[t].w));
                *(uint4*)(dB + n * STR + k4 * 4) = u;
            }
            __syncthreads();
        }
    }

    // ---- epilogue: bias + store (+ fp16 mirror) + fused BN stats ----
    float ssum[NT][2], sq[NT][2];
#pragma unroll
    for (int nt = 0; nt < NT; nt++) {
        ssum[nt][0] = ssum[nt][1] = 0.f;
        sq[nt][0] = sq[nt][1] = 0.f;
    }
#pragma unroll
    for (int mt = 0; mt < 2; mt++) {
        int rA2 = row0 + m0 + mt * 16 + g;
        int rB2 = rA2 + 8;
#pragma unroll
        for (int nt = 0; nt < NT; nt++) {
            int col = n0 + nt * 8 + tig * 2;
            float b0 = bias[col], b1 = bias[col + 1];
            float o00 = acc[mt][nt][0] + b0, o01 = acc[mt][nt][1] + b1;
            float o10 = acc[mt][nt][2] + b0, o11 = acc[mt][nt][3] + b1;
            if (rA2 < NN) {
                *(float2*)(outp + (size_t)rA2 * COUT + col) = make_float2(o00, o01);
                if (COUT == 128)
                    *(__half2*)(g_h16 + (size_t)rA2 * 128 + col) = __floats2half2_rn(o00, o01);
                ssum[nt][0] += o00; sq[nt][0] += o00 * o00;
                ssum[nt][1] += o01; sq[nt][1] += o01 * o01;
            }
            if (rB2 < NN) {
                *(float2*)(outp + (size_t)rB2 * COUT + col) = make_float2(o10, o11);
                if (COUT == 128)
                    *(__half2*)(g_h16 + (size_t)rB2 * 128 + col) = __floats2half2_rn(o10, o11);
                ssum[nt][0] += o10; sq[nt][0] += o10 * o10;
                ssum[nt][1] += o11; sq[nt][1] += o11 * o11;
            }
        }
    }
#pragma unroll
    for (int nt = 0; nt < NT; nt++)
#pragma unroll
        for (int j = 0; j < 2; j++) {
            float s = ssum[nt][j], q = sq[nt][j];
#pragma unroll
            for (int off = 4; off < 32; off <<= 1) {
                s += __shfl_xor_sync(0xFFFFFFFFu, s, off);
                q += __shfl_xor_sync(0xFFFFFFFFu, q, off);
            }
            if (g == 0) {
                int col = n0 + nt * 8 + tig * 2 + j;
                atomicAdd(&g_sum[col], s);
                atomicAdd(&g_ssq[col], q);
            }
        }
}

// ================= BN finalize + final norm pass =================
__global__ void bnfinal_kernel(const float* __restrict__ gamma,
                               const float* __restrict__ beta, int C) {
    int c = threadIdx.x;
    if (c < C) {
        float m = g_sum[c] * (1.0f / (float)NN);
        float v = g_ssq[c] * (1.0f / (float)NN) - m * m;
        float s = gamma[c] * rsqrtf(v + EPS);
        g_scale[c] = s;
        g_shift[c] = beta[c] - m * s;
    }
}
template <bool RELU, int C>
__global__ void norm_kernel(const float* __restrict__ inp, float* __restrict__ outp) {
    const int total4 = NN * C / 4;
    const float4* p4 = (const float4*)inp;
    float4* o4 = (float4*)outp;
    for (int i = blockIdx.x * blockDim.x + threadIdx.x; i < total4;
         i += gridDim.x * blockDim.x) {
        int c = (i * 4) & (C - 1);
        float4 v = p4[i];
        float4 sc = *(const float4*)(g_scale + c);
        float4 sh = *(const float4*)(g_shift + c);
        float4 r;
        r.x = fmaf(v.x, sc.x, sh.x); r.y = fmaf(v.y, sc.y, sh.y);
        r.z = fmaf(v.z, sc.z, sh.z); r.w = fmaf(v.w, sc.w, sh.w);
        if (RELU) {
            r.x = fmaxf(r.x, 0.f); r.y = fmaxf(r.y, 0.f);
            r.z = fmaxf(r.z, 0.f); r.w = fmaxf(r.w, 0.f);
        }
        o4[i] = r;
    }
}

// ================= launch =================
extern "C" void kernel_launch(void* const* d_in, const int* in_sizes, int n_in,
                              void* d_out, int out_size) {
    const float* x    = (const float*)d_in[0];
    const int*   ei   = (const int*)d_in[1];
    const int*   esrc = ei;
    const int*   edst = ei + NE;
    const float* Wl0 = (const float*)d_in[2];
    const float* bl0 = (const float*)d_in[3];
    const float* Wr0 = (const float*)d_in[4];
    const float* ga0 = (const float*)d_in[5];
    const float* be0 = (const float*)d_in[6];
    const float* Wl1 = (const float*)d_in[7];
    const float* bl1 = (const float*)d_in[8];
    const float* Wr1 = (const float*)d_in[9];
    const float* ga1 = (const float*)d_in[10];
    const float* be1 = (const float*)d_in[11];
    const float* Wl2 = (const float*)d_in[12];
    const float* bl2 = (const float*)d_in[13];
    const float* Wr2 = (const float*)d_in[14];
    const float* ga2 = (const float*)d_in[15];
    const float* be2 = (const float*)d_in[16];
    float* out = (float*)d_out;

    const int smem128 = (2 * 128 * 36 + 2 * 128 * 36) * sizeof(float);  // 73728
    const int smem64  = (2 * 128 * 36 + 2 * 64 * 36) * sizeof(float);   // 55296
    cudaFuncSetAttribute(gemm_mma_kernel<128, false>, cudaFuncAttributeMaxDynamicSharedMemorySize, smem128);
    cudaFuncSetAttribute(gemm_mma_kernel<128, true>,  cudaFuncAttributeMaxDynamicSharedMemorySize, smem128);
    cudaFuncSetAttribute(gemm_mma_kernel<64, true>,   cudaFuncAttributeMaxDynamicSharedMemorySize, smem64);

    float *preA = nullptr, *preB = nullptr, *aggp = nullptr;
    cudaGetSymbolAddress((void**)&preA, g_preA);
    cudaGetSymbolAddress((void**)&preB, g_preB);
    cudaGetSymbolAddress((void**)&aggp, g_agg);

    // ---- CSR build + fp16 mirror of x ----
    zero_cnt_kernel<<<(NN + 255) / 256, 256>>>();
    hist_kernel<<<NE / 256, 256>>>(edst);
    scan_kernel<<<1, 1024>>>();
    fill_kernel<<<NE / 256, 256>>>(esrc, edst);
    x2h_kernel<<<(NN * 32 + 255) / 256, 256>>>(x);

    const int aggBlocks = NN / 8;
    const int gemmBlocks = (NN + 127) / 128;

    // ---- layer 0: x -> preA (gemm writes fp16 mirror of preA) ----
    agg_kernel<false><<<aggBlocks, 256>>>();
    gemm_mma_kernel<128, false><<<gemmBlocks, 256, smem128>>>(aggp, x, Wl0, Wr0, bl0, preA);
    bnfinal_kernel<<<1, 128>>>(ga0, be0, 128);

    // ---- layer 1: relu(bn(preA)) -> preB (gemm writes fp16 mirror of preB) ----
    agg_kernel<true><<<aggBlocks, 256>>>();
    gemm_mma_kernel<128, true><<<gemmBlocks, 256, smem128>>>(aggp, preA, Wl1, Wr1, bl1, preB);
    bnfinal_kernel<<<1, 128>>>(ga1, be1, 128);

    // ---- layer 2: relu(bn(preB)) -> preA (64 cols) ----
    agg_kernel<true><<<aggBlocks, 256>>>();
    gemm_mma_kernel<64, true><<<gemmBlocks, 256, smem64>>>(aggp, preB, Wl2, Wr2, bl2, preA);
    bnfinal_kernel<<<1, 64>>>(ga2, be2, 64);

    // ---- final normalize (no relu) ----
    norm_kernel<false, 64><<<2048, 256>>>(preA, out);
}

// round 11
// speedup vs baseline: 1.1160x; 1.0365x over previous
#include <cuda_runtime.h>
#include <cuda_fp16.h>
#include <cstdint>
#include <math.h>

#define NN 100000
#define NE 1600000
#define EPS 1e-5f

// ================= device scratch =================
__device__ int   g_cnt[NN];
__device__ int   g_off[NN + 1];
__device__ int   g_cur[NN];
__device__ float g_inv[NN];
__device__ int   g_col[NE];
__device__ float g_agg[(size_t)NN * 128];
__device__ float g_preA[(size_t)NN * 128];
__device__ float g_preB[(size_t)NN * 128];
__device__ float g_sum[128];
__device__ float g_ssq[128];
__device__ float g_scale[128];
__device__ float g_shift[128];

__device__ __forceinline__ uint32_t h2u(float a, float b) {
    __half2 h = __floats2half2_rn(a, b);
    return *(uint32_t*)&h;
}

// ================= CSR build =================
__global__ void zero_cnt_kernel() {
    int i = blockIdx.x * blockDim.x + threadIdx.x;
    if (i < NN) g_cnt[i] = 0;
}
__global__ void hist_kernel(const int* __restrict__ dst) {
    int e = blockIdx.x * blockDim.x + threadIdx.x;
    if (e < NE) atomicAdd(&g_cnt[dst[e]], 1);
}
__global__ void scan_kernel() {
    __shared__ int s[1024];
    const int t = threadIdx.x;
    const int chunk = (NN + 1023) / 1024;
    int start = t * chunk;
    int end = start + chunk; if (end > NN) end = NN;
    if (start > NN) start = NN;
    int sum = 0;
    for (int i = start; i < end; i++) sum += g_cnt[i];
    s[t] = sum;
    __syncthreads();
    for (int off = 1; off < 1024; off <<= 1) {
        int v = (t >= off) ? s[t - off] : 0;
        __syncthreads();
        s[t] += v;
        __syncthreads();
    }
    int excl = (t == 0) ? 0 : s[t - 1];
    for (int i = start; i < end; i++) {
        int c = g_cnt[i];
        g_off[i] = excl;
        g_cur[i] = excl;
        g_inv[i] = 1.0f / fmaxf((float)c, 1.0f);
        excl += c;
    }
    if (t == 1023) g_off[NN] = s[1023];
}
__global__ void fill_kernel(const int* __restrict__ src, const int* __restrict__ dst) {
    int e = blockIdx.x * blockDim.x + threadIdx.x;
    if (e < NE) {
        int d = dst[e];
        int p = atomicAdd(&g_cur[d], 1);
        g_col[p] = src[e];
    }
}

// ====== mean aggregation (warp/node), fused BN+ReLU, fused stats-zero ======
template <bool FUSE>
__global__ void agg_kernel(const float* __restrict__ hin) {
    if (blockIdx.x == 0 && threadIdx.x < 128) {   // zero next layer's BN stats
        g_sum[threadIdx.x] = 0.f;
        g_ssq[threadIdx.x] = 0.f;
    }
    int w = (blockIdx.x * blockDim.x + threadIdx.x) >> 5;
    if (w >= NN) return;
    int lane = threadIdx.x & 31;
    const float4* h4 = (const float4*)hin;
    float4 sc, sh;
    if (FUSE) {
        sc = *(const float4*)(g_scale + lane * 4);
        sh = *(const float4*)(g_shift + lane * 4);
    }
    float4 acc = make_float4(0.f, 0.f, 0.f, 0.f);
    int e0 = g_off[w], e1 = g_off[w + 1];
    for (int j = e0; j < e1; j++) {
        int s = g_col[j];
        float4 v = __ldg(&h4[(size_t)s * 32 + lane]);
        if (FUSE) {
            v.x = fmaxf(fmaf(v.x, sc.x, sh.x), 0.f);
            v.y = fmaxf(fmaf(v.y, sc.y, sh.y), 0.f);
            v.z = fmaxf(fmaf(v.z, sc.z, sh.z), 0.f);
            v.w = fmaxf(fmaf(v.w, sc.w, sh.w), 0.f);
        }
        acc.x += v.x; acc.y += v.y; acc.z += v.z; acc.w += v.w;
    }
    float iv = g_inv[w];
    ((float4*)g_agg)[(size_t)w * 32 + lane] =
        make_float4(acc.x * iv, acc.y * iv, acc.z * iv, acc.w * iv);
}

// ============== fp16 mma.sync (m16n8k16) dual-GEMM, K-streamed ==============
// Block: 128 rows x COUT cols, K=256 in 8 chunks of 32. A+B chunks double-
// buffered as half2 k-pairs: rows of 16 uint32 + 4 pad (stride 20 == 4 mod 32
// -> conflict-free 4g+tig fragment LDS). 2 k-steps of K=16 per chunk.
// Fused bias + BN stats epilogue; FUSE applies BN+ReLU to root input Ah.
template <int COUT, bool FUSE>
__global__ __launch_bounds__(256) void gemm_mma_kernel(
    const float* __restrict__ Aagg, const float* __restrict__ Ah,
    const float* __restrict__ Wl, const float* __restrict__ Wr,
    const float* __restrict__ bias, float* __restrict__ outp)
{
    constexpr int STRW = 20;                   // uint32 per row (16 data + 4 pad)
    constexpr int NT = COUT / 16;              // n-tiles per warp (8 or 4)
    constexpr int BITER = COUT / 32;           // B-chunk uint2 iters (4 or 2)
    extern __shared__ uint32_t smem32[];
    uint32_t* As = smem32;                     // [2][128][20]
    uint32_t* Bs = smem32 + 2 * 128 * STRW;    // [2][COUT][20]

    const int tid = threadIdx.x, wid = tid >> 5, lane = tid & 31;
    const int g = lane >> 2, tig = lane & 3;
    const int row0 = blockIdx.x * 128;
    const int m0 = (wid >> 1) * 32;
    const int n0 = (wid & 1) * (COUT / 2);

    // ---- stage chunk 0: A (agg) + B (Wl) ----
#pragma unroll
    for (int t = 0; t < 4; t++) {
        int i = tid + t * 256;
        int row = i >> 3, q = i & 7;           // q: which float4 of the 32 floats
        int grow = row0 + row;
        float4 v = make_float4(0.f, 0.f, 0.f, 0.f);
        if (grow < NN) v = *(const float4*)(Aagg + (size_t)grow * 128 + q * 4);
        uint2 u = make_uint2(h2u(v.x, v.y), h2u(v.z, v.w));
        *(uint2*)(As + row * STRW + q * 2) = u;
    }
#pragma unroll
    for (int t = 0; t < BITER; t++) {
        int i = tid + t * 256;
        int n = i >> 3, q = i & 7;
        float4 v = *(const float4*)(Wl + n * 128 + q * 4);
        uint2 u = make_uint2(h2u(v.x, v.y), h2u(v.z, v.w));
        *(uint2*)(Bs + n * STRW + q * 2) = u;
    }
    __syncthreads();

    float acc[2][NT][4];
#pragma unroll
    for (int mt = 0; mt < 2; mt++)
#pragma unroll
        for (int nt = 0; nt < NT; nt++)
#pragma unroll
            for (int j = 0; j < 4; j++) acc[mt][nt][j] = 0.f;

    for (int c = 0; c < 8; c++) {
        float4 rA[4], rB[BITER];
        if (c < 7) {
            int cn = c + 1;
            const float* src = (cn < 4) ? Aagg : Ah;
            const float* W = (cn < 4) ? Wl : Wr;
            const bool dofuse = FUSE && (cn >= 4);
            int koff = (cn & 3) * 32;
#pragma unroll
            for (int t = 0; t < 4; t++) {
                int i = tid + t * 256;
                int row = i >> 3, q = i & 7;
                int grow = row0 + row;
                rA[t] = make_float4(0.f, 0.f, 0.f, 0.f);
                if (grow < NN) {
                    float4 v = *(const float4*)(src + (size_t)grow * 128 + koff + q * 4);
                    if (dofuse) {
                        float4 sc = *(const float4*)(g_scale + koff + q * 4);
                        float4 sh = *(const float4*)(g_shift + koff + q * 4);
                        v.x = fmaxf(fmaf(v.x, sc.x, sh.x), 0.f);
                        v.y = fmaxf(fmaf(v.y, sc.y, sh.y), 0.f);
                        v.z = fmaxf(fmaf(v.z, sc.z, sh.z), 0.f);
                        v.w = fmaxf(fmaf(v.w, sc.w, sh.w), 0.f);
                    }
                    rA[t] = v;
                }
            }
#pragma unroll
            for (int t = 0; t < BITER; t++) {
                int i = tid + t * 256;
                int n = i >> 3, q = i & 7;
                rB[t] = *(const float4*)(W + n * 128 + koff + q * 4);
            }
        }
        const uint32_t* Ab = As + (c & 1) * 128 * STRW;
        const uint32_t* Bb = Bs + (c & 1) * COUT * STRW;
#pragma unroll
        for (int ks = 0; ks < 2; ks++) {       // 2 k-steps of K=16 (8 k-pairs)
            const int kk2 = ks * 8;
            uint32_t a[2][4], b[NT][2];
#pragma unroll
            for (int mt = 0; mt < 2; mt++) {
                const uint32_t* ap = Ab + (m0 + mt * 16 + g) * STRW + kk2 + tig;
                a[mt][0] = ap[0];
                a[mt][1] = ap[8 * STRW];
                a[mt][2] = ap[4];
                a[mt][3] = ap[8 * STRW + 4];
            }
#pragma unroll
            for (int nt = 0; nt < NT; nt++) {
                const uint32_t* bp = Bb + (n0 + nt * 8 + g) * STRW + kk2 + tig;
                b[nt][0] = bp[0];
                b[nt][1] = bp[4];
            }
#pragma unroll
            for (int mt = 0; mt < 2; mt++)
#pragma unroll
                for (int nt = 0; nt < NT; nt++)
                    asm volatile(
                        "mma.sync.aligned.m16n8k16.row.col.f32.f16.f16.f32 "
                        "{%0,%1,%2,%3}, {%4,%5,%6,%7}, {%8,%9}, {%0,%1,%2,%3};"
                        : "+f"(acc[mt][nt][0]), "+f"(acc[mt][nt][1]),
                          "+f"(acc[mt][nt][2]), "+f"(acc[mt][nt][3])
                        : "r"(a[mt][0]), "r"(a[mt][1]), "r"(a[mt][2]), "r"(a[mt][3]),
                          "r"(b[nt][0]), "r"(b[nt][1]));
        }
        __syncthreads();
        if (c < 7) {
            uint32_t* dA = As + ((c + 1) & 1) * 128 * STRW;
            uint32_t* dB = Bs + ((c + 1) & 1) * COUT * STRW;
#pragma unroll
            for (int t = 0; t < 4; t++) {
                int i = tid + t * 256;
                int row = i >> 3, q = i & 7;
                uint2 u = make_uint2(h2u(rA[t].x, rA[t].y), h2u(rA[t].z, rA[t].w));
                *(uint2*)(dA + row * STRW + q * 2) = u;
            }
#pragma unroll
            for (int t = 0; t < BITER; t++) {
                int i = tid + t * 256;
                int n = i >> 3, q = i & 7;
                uint2 u = make_uint2(h2u(rB[t].x, rB[t].y), h2u(rB[t].z, rB[t].w));
                *(uint2*)(dB + n * STRW + q * 2) = u;
            }
            __syncthreads();
        }
    }

    // ---- epilogue: bias + store + fused BN stats ----
    float ssum[NT][2], sq[NT][2];
#pragma unroll
    for (int nt = 0; nt < NT; nt++) {
        ssum[nt][0] = ssum[nt][1] = 0.f;
        sq[nt][0] = sq[nt][1] = 0.f;
    }
#pragma unroll
    for (int mt = 0; mt < 2; mt++) {
        int rA2 = row0 + m0 + mt * 16 + g;
        int rB2 = rA2 + 8;
#pragma unroll
        for (int nt = 0; nt < NT; nt++) {
            int col = n0 + nt * 8 + tig * 2;
            float b0 = bias[col], b1 = bias[col + 1];
            float o00 = acc[mt][nt][0] + b0, o01 = acc[mt][nt][1] + b1;
            float o10 = acc[mt][nt][2] + b0, o11 = acc[mt][nt][3] + b1;
            if (rA2 < NN) {
                *(float2*)(outp + (size_t)rA2 * COUT + col) = make_float2(o00, o01);
                ssum[nt][0] += o00; sq[nt][0] += o00 * o00;
                ssum[nt][1] += o01; sq[nt][1] += o01 * o01;
            }
            if (rB2 < NN) {
                *(float2*)(outp + (size_t)rB2 * COUT + col) = make_float2(o10, o11);
                ssum[nt][0] += o10; sq[nt][0] += o10 * o10;
                ssum[nt][1] += o11; sq[nt][1] += o11 * o11;
            }
        }
    }
#pragma unroll
    for (int nt = 0; nt < NT; nt++)
#pragma unroll
        for (int j = 0; j < 2; j++) {
            float s = ssum[nt][j], q = sq[nt][j];
#pragma unroll
            for (int off = 4; off < 32; off <<= 1) {
                s += __shfl_xor_sync(0xFFFFFFFFu, s, off);
                q += __shfl_xor_sync(0xFFFFFFFFu, q, off);
            }
            if (g == 0) {
                int col = n0 + nt * 8 + tig * 2 + j;
                atomicAdd(&g_sum[col], s);
                atomicAdd(&g_ssq[col], q);
            }
        }
}

// ================= BN finalize + final norm pass =================
__global__ void bnfinal_kernel(const float* __restrict__ gamma,
                               const float* __restrict__ beta, int C) {
    int c = threadIdx.x;
    if (c < C) {
        float m = g_sum[c] * (1.0f / (float)NN);
        float v = g_ssq[c] * (1.0f / (float)NN) - m * m;
        float s = gamma[c] * rsqrtf(v + EPS);
        g_scale[c] = s;
        g_shift[c] = beta[c] - m * s;
    }
}
template <bool RELU, int C>
__global__ void norm_kernel(const float* __restrict__ inp, float* __restrict__ outp) {
    const int total4 = NN * C / 4;
    const float4* p4 = (const float4*)inp;
    float4* o4 = (float4*)outp;
    for (int i = blockIdx.x * blockDim.x + threadIdx.x; i < total4;
         i += gridDim.x * blockDim.x) {
        int c = (i * 4) & (C - 1);
        float4 v = p4[i];
        float4 sc = *(const float4*)(g_scale + c);
        float4 sh = *(const float4*)(g_shift + c);
        float4 r;
        r.x = fmaf(v.x, sc.x, sh.x); r.y = fmaf(v.y, sc.y, sh.y);
        r.z = fmaf(v.z, sc.z, sh.z); r.w = fmaf(v.w, sc.w, sh.w);
        if (RELU) {
            r.x = fmaxf(r.x, 0.f); r.y = fmaxf(r.y, 0.f);
            r.z = fmaxf(r.z, 0.f); r.w = fmaxf(r.w, 0.f);
        }
        o4[i] = r;
    }
}

// ================= launch =================
extern "C" void kernel_launch(void* const* d_in, const int* in_sizes, int n_in,
                              void* d_out, int out_size) {
    const float* x    = (const float*)d_in[0];
    const int*   ei   = (const int*)d_in[1];
    const int*   esrc = ei;
    const int*   edst = ei + NE;
    const float* Wl0 = (const float*)d_in[2];
    const float* bl0 = (const float*)d_in[3];
    const float* Wr0 = (const float*)d_in[4];
    const float* ga0 = (const float*)d_in[5];
    const float* be0 = (const float*)d_in[6];
    const float* Wl1 = (const float*)d_in[7];
    const float* bl1 = (const float*)d_in[8];
    const float* Wr1 = (const float*)d_in[9];
    const float* ga1 = (const float*)d_in[10];
    const float* be1 = (const float*)d_in[11];
    const float* Wl2 = (const float*)d_in[12];
    const float* bl2 = (const float*)d_in[13];
    const float* Wr2 = (const float*)d_in[14];
    const float* ga2 = (const float*)d_in[15];
    const float* be2 = (const float*)d_in[16];
    float* out = (float*)d_out;

    const int smem128 = (2 * 128 * 20 + 2 * 128 * 20) * 4;  // 40960
    const int smem64  = (2 * 128 * 20 + 2 * 64 * 20) * 4;   // 30720
    cudaFuncSetAttribute(gemm_mma_kernel<128, false>, cudaFuncAttributeMaxDynamicSharedMemorySize, smem128);
    cudaFuncSetAttribute(gemm_mma_kernel<128, true>,  cudaFuncAttributeMaxDynamicSharedMemorySize, smem128);
    cudaFuncSetAttribute(gemm_mma_kernel<64, true>,   cudaFuncAttributeMaxDynamicSharedMemorySize, smem64);

    float *preA = nullptr, *preB = nullptr, *aggp = nullptr;
    cudaGetSymbolAddress((void**)&preA, g_preA);
    cudaGetSymbolAddress((void**)&preB, g_preB);
    cudaGetSymbolAddress((void**)&aggp, g_agg);

    // ---- CSR build ----
    zero_cnt_kernel<<<(NN + 255) / 256, 256>>>();
    hist_kernel<<<NE / 256, 256>>>(edst);
    scan_kernel<<<1, 1024>>>();
    fill_kernel<<<NE / 256, 256>>>(esrc, edst);

    const int aggBlocks = NN / 8;
    const int gemmBlocks = (NN + 127) / 128;

    // ---- layer 0: x -> preA ----
    agg_kernel<false><<<aggBlocks, 256>>>(x);
    gemm_mma_kernel<128, false><<<gemmBlocks, 256, smem128>>>(aggp, x, Wl0, Wr0, bl0, preA);
    bnfinal_kernel<<<1, 128>>>(ga0, be0, 128);

    // ---- layer 1: relu(bn(preA)) -> preB ----
    agg_kernel<true><<<aggBlocks, 256>>>(preA);
    gemm_mma_kernel<128, true><<<gemmBlocks, 256, smem128>>>(aggp, preA, Wl1, Wr1, bl1, preB);
    bnfinal_kernel<<<1, 128>>>(ga1, be1, 128);

    // ---- layer 2: relu(bn(preB)) -> preA (64 cols) ----
    agg_kernel<true><<<aggBlocks, 256>>>(preB);
    gemm_mma_kernel<64, true><<<gemmBlocks, 256, smem64>>>(aggp, preB, Wl2, Wr2, bl2, preA);
    bnfinal_kernel<<<1, 64>>>(ga2, be2, 64);

    // ---- final normalize (no relu) ----
    norm_kernel<false, 64><<<2048, 256>>>(preA, out);
}